// round 9
// baseline (speedup 1.0000x reference)
#include <cuda_runtime.h>

#define NB 8192
#define NP 4849
#define PPAD 4864      // padded param row stride (38*128, float4-aligned rows)
#define NH 96
#define NSTEPS 20

// Scratch (device globals: allocation-free per harness rules)
__device__ float g_h[NB * NH];                      // 3.1 MB   hyper hidden
__device__ float g_params[(size_t)NB * PPAD];       // 159 MB   per-sample flat params

typedef unsigned long long ull;

union F4U { float4 f4; ull u2[2]; float f[4]; };
union U2  { ull u; float2 f; };

__device__ __forceinline__ ull ffma2(ull a, ull b, ull c) {
    ull d;
    asm("fma.rn.f32x2 %0, %1, %2, %3;" : "=l"(d) : "l"(a), "l"(b), "l"(c));
    return d;
}
__device__ __forceinline__ ull fadd2(ull a, ull b) {
    ull d;
    asm("add.rn.f32x2 %0, %1, %2;" : "=l"(d) : "l"(a), "l"(b));
    return d;
}
__device__ __forceinline__ ull pack2(float lo, float hi) {
    ull r;
    asm("mov.b64 %0, {%1, %2};" : "=l"(r) : "f"(lo), "f"(hi));
    return r;
}
__device__ __forceinline__ float sigmoidf(float z) {
    return 1.0f / (1.0f + __expf(-z));
}

// ---------------------------------------------------------------------------
// Kernel 0: h[b,k] = relu(hw1[k,0]*x[b] + hw1[k,1]*c[b] + hb1[k])
// ---------------------------------------------------------------------------
__global__ void hyper_h_kernel(const float* __restrict__ x, const float* __restrict__ c,
                               const float* __restrict__ hw1, const float* __restrict__ hb1) {
    int idx = blockIdx.x * blockDim.x + threadIdx.x;
    if (idx >= NB * NH) return;
    int b = idx / NH;
    int k = idx - b * NH;
    float v = fmaf(hw1[2 * k], x[b], fmaf(hw1[2 * k + 1], c[b], hb1[k]));
    g_h[idx] = fmaxf(v, 0.0f);
}

// ---------------------------------------------------------------------------
// Kernel 1: g_params[b, j] = hb2[j] + sum_k g_h[b,k] * hw2[j,k]
// M=8192, N=4849->4864, K=96.  64x128 tile, 4x8 per thread, FFMA2 mainloop.
// A stored DUPLICATED in smem so ld.shared.b64 gives (a,a) pairs for free;
// B column pairs come straight out of float4 loads (register-pair reinterpret).
// ---------------------------------------------------------------------------
#define BM 64
#define BN 128
#define BK 32
#define LDA (2 * BM + 2)   // 130 floats: rows stay 8B-aligned, 2-way STS conflict only
#define LDB (BN + 4)       // 132

__global__ __launch_bounds__(256, 3) void hyper_gemm_kernel(const float* __restrict__ hw2,
                                                            const float* __restrict__ hb2) {
    __shared__ __align__(16) float As2[BK][LDA];   // duplicated A: As2[kk][2m]=As2[kk][2m+1]
    __shared__ __align__(16) float Bs[BK][LDB];

    const int b0 = blockIdx.x * BM;
    const int j0 = blockIdx.y * BN;
    const int tid = threadIdx.x;
    const int tr = tid >> 4;    // 0..15 -> output rows tr*4 .. tr*4+3
    const int tc = tid & 15;    // 0..15 -> output cols tc*8 .. tc*8+7

    ull acc2[4][4];
#pragma unroll
    for (int i = 0; i < 4; i++)
#pragma unroll
        for (int j = 0; j < 4; j++) acc2[i][j] = 0ULL;

    for (int k0 = 0; k0 < NH; k0 += BK) {
        // A tile, duplicated: coalesced over kk
#pragma unroll
        for (int l = 0; l < (BM * BK) / 256; l++) {
            int idx = tid + l * 256;
            int m = idx >> 5;
            int kk = idx & 31;
            float v = g_h[(b0 + m) * NH + k0 + kk];
            *(float2*)&As2[kk][2 * m] = make_float2(v, v);
        }
        // B tile: coalesced over kk
#pragma unroll
        for (int l = 0; l < (BN * BK) / 256; l++) {
            int idx = tid + l * 256;
            int j = idx >> 5;
            int kk = idx & 31;
            int jj = j0 + j;
            Bs[kk][j] = (jj < NP) ? hw2[jj * NH + k0 + kk] : 0.0f;
        }
        __syncthreads();

#pragma unroll 8
        for (int kk = 0; kk < BK; kk++) {
            ull a2[4];
#pragma unroll
            for (int i = 0; i < 4; i++)
                a2[i] = *(const ull*)&As2[kk][2 * (tr * 4 + i)];   // broadcast read

            F4U bu0, bu1;
            bu0.f4 = *(const float4*)&Bs[kk][tc * 8];
            bu1.f4 = *(const float4*)&Bs[kk][tc * 8 + 4];
            ull b2[4] = {bu0.u2[0], bu0.u2[1], bu1.u2[0], bu1.u2[1]};

#pragma unroll
            for (int i = 0; i < 4; i++)
#pragma unroll
                for (int j = 0; j < 4; j++)
                    acc2[i][j] = ffma2(a2[i], b2[j], acc2[i][j]);
        }
        __syncthreads();
    }

    float bias[8];
#pragma unroll
    for (int j = 0; j < 8; j++) {
        int jj = j0 + tc * 8 + j;
        bias[j] = (jj < NP) ? hb2[jj] : 0.0f;
    }
#pragma unroll
    for (int i = 0; i < 4; i++) {
        float r[8];
#pragma unroll
        for (int j = 0; j < 4; j++) {
            U2 t; t.u = acc2[i][j];
            r[2 * j]     = t.f.x + bias[2 * j];
            r[2 * j + 1] = t.f.y + bias[2 * j + 1];
        }
        float* o = &g_params[(size_t)(b0 + tr * 4 + i) * PPAD + j0 + tc * 8];
        *(float4*)o       = make_float4(r[0], r[1], r[2], r[3]);
        *(float4*)(o + 4) = make_float4(r[4], r[5], r[6], r[7]);
    }
}

// ---------------------------------------------------------------------------
// Kernel 2: 20 Adam steps per sample.  g = dE/dy via forward + JVP through the
// 48-wide swish MLP.  96 threads / 2 samples per block; thread i owns row i of
// w1 and w2 in registers (as f32x2 pairs).  Even/odd-k sums packed in FFMA2.
// ---------------------------------------------------------------------------
__global__ __launch_bounds__(96, 4) void adam_kernel(float* __restrict__ out) {
    __shared__ __align__(16) float h0s[2][48];
    __shared__ __align__(16) float dh0s[2][48];
    __shared__ __align__(16) float h1s[2][48];
    __shared__ __align__(16) float dh1s[2][48];
    __shared__ __align__(16) float part[2][48];

    const int tid = threadIdx.x;
    const int s = tid / 48;          // sample slot within block
    const int i = tid - s * 48;      // row 0..47
    const int sample = blockIdx.x * 2 + s;

    const float* p = g_params + (size_t)sample * PPAD;

    // Layout: w0[48] b0[48] w1[48x48] b1[48] w2[48x48] b2[48] w3[48] b3
    const float w0i = p[i];
    const float b0i = p[48 + i];
    const float b1i = p[2400 + i];
    const float b2i = p[4752 + i];
    const float w3i = p[4800 + i];

    ull w1p[24], w2p[24];   // (w[2k], w[2k+1]) pairs
    {
        const float4* p1 = (const float4*)(p + 96 + i * 48);
        const float4* p2 = (const float4*)(p + 2448 + i * 48);
#pragma unroll
        for (int q = 0; q < 12; q++) {
            F4U a; a.f4 = p1[q];
            w1p[2 * q] = a.u2[0]; w1p[2 * q + 1] = a.u2[1];
            F4U b; b.f4 = p2[q];
            w2p[2 * q] = b.u2[0]; w2p[2 * q + 1] = b.u2[1];
        }
    }

    float y = 0.0f, mA = 0.0f, vA = 0.0f, pb1 = 1.0f, pb2 = 1.0f;

#pragma unroll 1
    for (int t = 0; t < NSTEPS; t++) {
        // Layer 0 (scalar input): z0 = w0*y + b0 ; tangent dz0 = w0
        float z0 = fmaf(w0i, y, b0i);
        float s0 = sigmoidf(z0);
        h0s[s][i]  = z0 * s0;
        dh0s[s][i] = (s0 + z0 * s0 * (1.0f - s0)) * w0i;
        __syncthreads();

        // Layer 1: z1_i = b1_i + w1[i,:].h0 ; dz1_i = w1[i,:].dh0
        ull accF = pack2(b1i, 0.0f);
        ull accT = 0ULL;
        {
            const float4* h4 = (const float4*)h0s[s];
            const float4* d4 = (const float4*)dh0s[s];
#pragma unroll
            for (int q = 0; q < 12; q++) {
                F4U hv; hv.f4 = h4[q];
                F4U dv; dv.f4 = d4[q];
                accF = ffma2(w1p[2 * q],     hv.u2[0], accF);
                accF = ffma2(w1p[2 * q + 1], hv.u2[1], accF);
                accT = ffma2(w1p[2 * q],     dv.u2[0], accT);
                accT = ffma2(w1p[2 * q + 1], dv.u2[1], accT);
            }
        }
        U2 tF; tF.u = accF;
        U2 tT; tT.u = accT;
        float acc  = tF.f.x + tF.f.y;
        float dacc = tT.f.x + tT.f.y;

        float s1 = sigmoidf(acc);
        h1s[s][i]  = acc * s1;
        dh1s[s][i] = (s1 + acc * s1 * (1.0f - s1)) * dacc;
        __syncthreads();

        // Layer 2
        accF = pack2(b2i, 0.0f);
        accT = 0ULL;
        {
            const float4* h4 = (const float4*)h1s[s];
            const float4* d4 = (const float4*)dh1s[s];
#pragma unroll
            for (int q = 0; q < 12; q++) {
                F4U hv; hv.f4 = h4[q];
                F4U dv; dv.f4 = d4[q];
                accF = ffma2(w2p[2 * q],     hv.u2[0], accF);
                accF = ffma2(w2p[2 * q + 1], hv.u2[1], accF);
                accT = ffma2(w2p[2 * q],     dv.u2[0], accT);
                accT = ffma2(w2p[2 * q + 1], dv.u2[1], accT);
            }
        }
        tF.u = accF; tT.u = accT;
        acc  = tF.f.x + tF.f.y;
        dacc = tT.f.x + tT.f.y;

        float s2 = sigmoidf(acc);
        // output-layer tangent contribution (b3 drops out of the gradient)
        part[s][i] = w3i * ((s2 + acc * s2 * (1.0f - s2)) * dacc);
        __syncthreads();

        // g = sum_i part_i  (redundant in all threads: deterministic, no extra barrier)
        ull gp = 0ULL;
        {
            const float4* q4 = (const float4*)part[s];
#pragma unroll
            for (int q = 0; q < 12; q++) {
                F4U pv; pv.f4 = q4[q];
                gp = fadd2(gp, pv.u2[0]);
                gp = fadd2(gp, pv.u2[1]);
            }
        }
        U2 tg; tg.u = gp;
        float g = tg.f.x + tg.f.y;

        // Adam update
        pb1 *= 0.9f;
        pb2 *= 0.999f;
        mA = 0.9f * mA + 0.1f * g;
        vA = 0.999f * vA + 0.001f * g * g;
        float mh = mA / (1.0f - pb1);
        float vh = vA / (1.0f - pb2);
        y -= 0.1f * mh / (sqrtf(vh) + 1e-8f);
    }

    if (i == 0) out[sample] = y;
}

// ---------------------------------------------------------------------------
extern "C" void kernel_launch(void* const* d_in, const int* in_sizes, int n_in,
                              void* d_out, int out_size) {
    const float* x   = (const float*)d_in[0];   // (8192,1)
    const float* c   = (const float*)d_in[1];   // (8192,1)
    const float* hw1 = (const float*)d_in[2];   // (96,2)
    const float* hb1 = (const float*)d_in[3];   // (96,)
    const float* hw2 = (const float*)d_in[4];   // (4849,96)
    const float* hb2 = (const float*)d_in[5];   // (4849,)
    float* out = (float*)d_out;                 // (8192,1)

    (void)in_sizes; (void)n_in; (void)out_size;

    hyper_h_kernel<<<(NB * NH + 255) / 256, 256>>>(x, c, hw1, hb1);

    dim3 grid(NB / BM, (NP + BN - 1) / BN);     // (128, 38)
    hyper_gemm_kernel<<<grid, 256>>>(hw2, hb2);

    adam_kernel<<<NB / 2, 96>>>(out);
}

// round 10
// speedup vs baseline: 1.0582x; 1.0582x over previous
#include <cuda_runtime.h>

#define NB 8192
#define NP 4849
#define PPAD 4864      // padded param row stride (38*128, float4-aligned rows)
#define NH 96
#define NSTEPS 20

// Scratch (device globals: allocation-free per harness rules)
__device__ float g_h[NB * NH];                      // 3.1 MB   hyper hidden
__device__ float g_params[(size_t)NB * PPAD];       // 159 MB   per-sample flat params

typedef unsigned long long ull;

union F4U { float4 f4; ull u2[2]; float f[4]; };
union U2  { ull u; float2 f; };

__device__ __forceinline__ ull ffma2(ull a, ull b, ull c) {
    ull d;
    asm("fma.rn.f32x2 %0, %1, %2, %3;" : "=l"(d) : "l"(a), "l"(b), "l"(c));
    return d;
}
__device__ __forceinline__ ull fadd2(ull a, ull b) {
    ull d;
    asm("add.rn.f32x2 %0, %1, %2;" : "=l"(d) : "l"(a), "l"(b));
    return d;
}
__device__ __forceinline__ ull pack2(float lo, float hi) {
    ull r;
    asm("mov.b64 %0, {%1, %2};" : "=l"(r) : "f"(lo), "f"(hi));
    return r;
}
__device__ __forceinline__ float sigmoidf(float z) {
    return 1.0f / (1.0f + __expf(-z));
}

// ---------------------------------------------------------------------------
// Kernel 0: h[b,k] = relu(hw1[k,0]*x[b] + hw1[k,1]*c[b] + hb1[k])
// ---------------------------------------------------------------------------
__global__ void hyper_h_kernel(const float* __restrict__ x, const float* __restrict__ c,
                               const float* __restrict__ hw1, const float* __restrict__ hb1) {
    int idx = blockIdx.x * blockDim.x + threadIdx.x;
    if (idx >= NB * NH) return;
    int b = idx / NH;
    int k = idx - b * NH;
    float v = fmaf(hw1[2 * k], x[b], fmaf(hw1[2 * k + 1], c[b], hb1[k]));
    g_h[idx] = fmaxf(v, 0.0f);
}

// ---------------------------------------------------------------------------
// Kernel 1: g_params[b, j] = hb2[j] + sum_k g_h[b,k] * hw2[j,k]
// M=8192, N=4849->4864, K=96.  64x128 tile, 4x8 per thread, FFMA2 mainloop.
// A stored DUPLICATED in smem so ld.shared.b64 gives (a,a) pairs for free;
// B column pairs come straight out of float4 loads (register-pair reinterpret).
// ---------------------------------------------------------------------------
#define BM 64
#define BN 128
#define BK 32
#define LDA (2 * BM + 2)   // 130 floats: rows stay 8B-aligned, 2-way STS conflict only
#define LDB (BN + 4)       // 132

__global__ __launch_bounds__(256, 3) void hyper_gemm_kernel(const float* __restrict__ hw2,
                                                            const float* __restrict__ hb2) {
    __shared__ __align__(16) float As2[BK][LDA];   // duplicated A: As2[kk][2m]=As2[kk][2m+1]
    __shared__ __align__(16) float Bs[BK][LDB];

    const int b0 = blockIdx.x * BM;
    const int j0 = blockIdx.y * BN;
    const int tid = threadIdx.x;
    const int tr = tid >> 4;    // 0..15 -> output rows tr*4 .. tr*4+3
    const int tc = tid & 15;    // 0..15 -> output cols tc*8 .. tc*8+7

    ull acc2[4][4];
#pragma unroll
    for (int i = 0; i < 4; i++)
#pragma unroll
        for (int j = 0; j < 4; j++) acc2[i][j] = 0ULL;

    for (int k0 = 0; k0 < NH; k0 += BK) {
        // A tile, duplicated: coalesced over kk
#pragma unroll
        for (int l = 0; l < (BM * BK) / 256; l++) {
            int idx = tid + l * 256;
            int m = idx >> 5;
            int kk = idx & 31;
            float v = g_h[(b0 + m) * NH + k0 + kk];
            *(float2*)&As2[kk][2 * m] = make_float2(v, v);
        }
        // B tile: coalesced over kk
#pragma unroll
        for (int l = 0; l < (BN * BK) / 256; l++) {
            int idx = tid + l * 256;
            int j = idx >> 5;
            int kk = idx & 31;
            int jj = j0 + j;
            Bs[kk][j] = (jj < NP) ? hw2[jj * NH + k0 + kk] : 0.0f;
        }
        __syncthreads();

#pragma unroll 8
        for (int kk = 0; kk < BK; kk++) {
            ull a2[4];
#pragma unroll
            for (int i = 0; i < 4; i++)
                a2[i] = *(const ull*)&As2[kk][2 * (tr * 4 + i)];   // broadcast read

            F4U bu0, bu1;
            bu0.f4 = *(const float4*)&Bs[kk][tc * 8];
            bu1.f4 = *(const float4*)&Bs[kk][tc * 8 + 4];
            ull b2[4] = {bu0.u2[0], bu0.u2[1], bu1.u2[0], bu1.u2[1]};

#pragma unroll
            for (int i = 0; i < 4; i++)
#pragma unroll
                for (int j = 0; j < 4; j++)
                    acc2[i][j] = ffma2(a2[i], b2[j], acc2[i][j]);
        }
        __syncthreads();
    }

    float bias[8];
#pragma unroll
    for (int j = 0; j < 8; j++) {
        int jj = j0 + tc * 8 + j;
        bias[j] = (jj < NP) ? hb2[jj] : 0.0f;
    }
#pragma unroll
    for (int i = 0; i < 4; i++) {
        float r[8];
#pragma unroll
        for (int j = 0; j < 4; j++) {
            U2 t; t.u = acc2[i][j];
            r[2 * j]     = t.f.x + bias[2 * j];
            r[2 * j + 1] = t.f.y + bias[2 * j + 1];
        }
        float* o = &g_params[(size_t)(b0 + tr * 4 + i) * PPAD + j0 + tc * 8];
        *(float4*)o       = make_float4(r[0], r[1], r[2], r[3]);
        *(float4*)(o + 4) = make_float4(r[4], r[5], r[6], r[7]);
    }
}

// ---------------------------------------------------------------------------
// Kernel 2: 20 Adam steps per sample.  g = dE/dy via forward + JVP through the
// 48-wide swish MLP.  96 threads / 2 samples per block; thread i owns row i of
// w1 and w2 in registers (as f32x2 pairs).  Even/odd-k sums packed in FFMA2.
// ---------------------------------------------------------------------------
__global__ __launch_bounds__(96, 4) void adam_kernel(float* __restrict__ out) {
    __shared__ __align__(16) float h0s[2][48];
    __shared__ __align__(16) float dh0s[2][48];
    __shared__ __align__(16) float h1s[2][48];
    __shared__ __align__(16) float dh1s[2][48];
    __shared__ __align__(16) float part[2][48];

    const int tid = threadIdx.x;
    const int s = tid / 48;          // sample slot within block
    const int i = tid - s * 48;      // row 0..47
    const int sample = blockIdx.x * 2 + s;

    const float* p = g_params + (size_t)sample * PPAD;

    // Layout: w0[48] b0[48] w1[48x48] b1[48] w2[48x48] b2[48] w3[48] b3
    const float w0i = p[i];
    const float b0i = p[48 + i];
    const float b1i = p[2400 + i];
    const float b2i = p[4752 + i];
    const float w3i = p[4800 + i];

    ull w1p[24], w2p[24];   // (w[2k], w[2k+1]) pairs
    {
        const float4* p1 = (const float4*)(p + 96 + i * 48);
        const float4* p2 = (const float4*)(p + 2448 + i * 48);
#pragma unroll
        for (int q = 0; q < 12; q++) {
            F4U a; a.f4 = p1[q];
            w1p[2 * q] = a.u2[0]; w1p[2 * q + 1] = a.u2[1];
            F4U b; b.f4 = p2[q];
            w2p[2 * q] = b.u2[0]; w2p[2 * q + 1] = b.u2[1];
        }
    }

    float y = 0.0f, mA = 0.0f, vA = 0.0f, pb1 = 1.0f, pb2 = 1.0f;

#pragma unroll 1
    for (int t = 0; t < NSTEPS; t++) {
        // Layer 0 (scalar input): z0 = w0*y + b0 ; tangent dz0 = w0
        float z0 = fmaf(w0i, y, b0i);
        float s0 = sigmoidf(z0);
        h0s[s][i]  = z0 * s0;
        dh0s[s][i] = (s0 + z0 * s0 * (1.0f - s0)) * w0i;
        __syncthreads();

        // Layer 1: z1_i = b1_i + w1[i,:].h0 ; dz1_i = w1[i,:].dh0
        ull accF = pack2(b1i, 0.0f);
        ull accT = 0ULL;
        {
            const float4* h4 = (const float4*)h0s[s];
            const float4* d4 = (const float4*)dh0s[s];
#pragma unroll
            for (int q = 0; q < 12; q++) {
                F4U hv; hv.f4 = h4[q];
                F4U dv; dv.f4 = d4[q];
                accF = ffma2(w1p[2 * q],     hv.u2[0], accF);
                accF = ffma2(w1p[2 * q + 1], hv.u2[1], accF);
                accT = ffma2(w1p[2 * q],     dv.u2[0], accT);
                accT = ffma2(w1p[2 * q + 1], dv.u2[1], accT);
            }
        }
        U2 tF; tF.u = accF;
        U2 tT; tT.u = accT;
        float acc  = tF.f.x + tF.f.y;
        float dacc = tT.f.x + tT.f.y;

        float s1 = sigmoidf(acc);
        h1s[s][i]  = acc * s1;
        dh1s[s][i] = (s1 + acc * s1 * (1.0f - s1)) * dacc;
        __syncthreads();

        // Layer 2
        accF = pack2(b2i, 0.0f);
        accT = 0ULL;
        {
            const float4* h4 = (const float4*)h1s[s];
            const float4* d4 = (const float4*)dh1s[s];
#pragma unroll
            for (int q = 0; q < 12; q++) {
                F4U hv; hv.f4 = h4[q];
                F4U dv; dv.f4 = d4[q];
                accF = ffma2(w2p[2 * q],     hv.u2[0], accF);
                accF = ffma2(w2p[2 * q + 1], hv.u2[1], accF);
                accT = ffma2(w2p[2 * q],     dv.u2[0], accT);
                accT = ffma2(w2p[2 * q + 1], dv.u2[1], accT);
            }
        }
        tF.u = accF; tT.u = accT;
        acc  = tF.f.x + tF.f.y;
        dacc = tT.f.x + tT.f.y;

        float s2 = sigmoidf(acc);
        // output-layer tangent contribution (b3 drops out of the gradient)
        part[s][i] = w3i * ((s2 + acc * s2 * (1.0f - s2)) * dacc);
        __syncthreads();

        // g = sum_i part_i  (redundant in all threads: deterministic, no extra barrier)
        ull gp = 0ULL;
        {
            const float4* q4 = (const float4*)part[s];
#pragma unroll
            for (int q = 0; q < 12; q++) {
                F4U pv; pv.f4 = q4[q];
                gp = fadd2(gp, pv.u2[0]);
                gp = fadd2(gp, pv.u2[1]);
            }
        }
        U2 tg; tg.u = gp;
        float g = tg.f.x + tg.f.y;

        // Adam update
        pb1 *= 0.9f;
        pb2 *= 0.999f;
        mA = 0.9f * mA + 0.1f * g;
        vA = 0.999f * vA + 0.001f * g * g;
        float mh = mA / (1.0f - pb1);
        float vh = vA / (1.0f - pb2);
        y -= 0.1f * mh / (sqrtf(vh) + 1e-8f);
    }

    if (i == 0) out[sample] = y;
}

// ---------------------------------------------------------------------------
extern "C" void kernel_launch(void* const* d_in, const int* in_sizes, int n_in,
                              void* d_out, int out_size) {
    const float* x   = (const float*)d_in[0];   // (8192,1)
    const float* c   = (const float*)d_in[1];   // (8192,1)
    const float* hw1 = (const float*)d_in[2];   // (96,2)
    const float* hb1 = (const float*)d_in[3];   // (96,)
    const float* hw2 = (const float*)d_in[4];   // (4849,96)
    const float* hb2 = (const float*)d_in[5];   // (4849,)
    float* out = (float*)d_out;                 // (8192,1)

    (void)in_sizes; (void)n_in; (void)out_size;

    hyper_h_kernel<<<(NB * NH + 255) / 256, 256>>>(x, c, hw1, hb1);

    dim3 grid(NB / BM, (NP + BN - 1) / BN);     // (128, 38)
    hyper_gemm_kernel<<<grid, 256>>>(hw2, hb2);

    adam_kernel<<<NB / 2, 96>>>(out);
}

// round 14
// speedup vs baseline: 1.3339x; 1.2605x over previous
#include <cuda_runtime.h>
#include <cuda_bf16.h>
#include <cstdint>

#define NB 8192
#define NPARAM 4849
#define NPPAD 4864     // padded N (38*128)
#define PPAD 4864      // param row stride
#define NH 96
#define K2 192         // [hi(96) | lo(96)] tf32 values stored as fp32
#define NSTEPS 20

// Device-global scratch (allocation-free per harness rules)
__device__ float g_params[(size_t)NB * PPAD];     // 159 MB
__device__ float g_A[(size_t)NB * K2];            // 6.3 MB  [ah | al]
__device__ float g_B[(size_t)NPPAD * K2];         // 3.7 MB  [bh | bl]

__device__ __forceinline__ float sigmoidf(float z) {
    return 1.0f / (1.0f + __expf(-z));
}

__device__ __forceinline__ float tf32_rn(float v) {
    uint32_t t;
    asm("cvt.rna.tf32.f32 %0, %1;" : "=r"(t) : "f"(v));
    return __uint_as_float(t);
}

// ---------------------------------------------------------------------------
// Prep A: h[b,k] = relu(hw1[k,0]*x[b] + hw1[k,1]*c[b] + hb1[k]); tf32 hi/lo split
// ---------------------------------------------------------------------------
__global__ void prep_a_kernel(const float* __restrict__ x, const float* __restrict__ c,
                              const float* __restrict__ hw1, const float* __restrict__ hb1) {
    int idx = blockIdx.x * blockDim.x + threadIdx.x;
    if (idx >= NB * NH) return;
    int b = idx / NH;
    int k = idx - b * NH;
    float v = fmaf(hw1[2 * k], x[b], fmaf(hw1[2 * k + 1], c[b], hb1[k]));
    v = fmaxf(v, 0.0f);
    float hi = tf32_rn(v);
    float lo = tf32_rn(v - hi);
    size_t base = (size_t)b * K2;
    g_A[base + k]      = hi;
    g_A[base + 96 + k] = lo;
}

// ---------------------------------------------------------------------------
// Prep B: tf32 hi/lo split of hw2 (rows >= NPARAM zeroed)
// ---------------------------------------------------------------------------
__global__ void prep_b_kernel(const float* __restrict__ hw2) {
    int idx = blockIdx.x * blockDim.x + threadIdx.x;
    if (idx >= NPPAD * NH) return;
    int j = idx / NH;
    int k = idx - j * NH;
    float w = (j < NPARAM) ? hw2[j * NH + k] : 0.0f;
    float hi = tf32_rn(w);
    float lo = tf32_rn(w - hi);
    size_t base = (size_t)j * K2;
    g_B[base + k]      = hi;
    g_B[base + 96 + k] = lo;
}

// ---------------------------------------------------------------------------
// 3xTF32 GEMM: g_params[b, j] = hb2[j] + (Ah+Al).(Bh+Bl)^T (al.bl dropped)
// mma.sync.m16n8k8.tf32 -> fp32.  128x128 tile per CTA, whole K resident.
// 8 warps: warp (wm 0..3, wn 0..1) computes 32x64.
// ---------------------------------------------------------------------------
#define SPITCH 196                        // fp32 pitch: bank=(4*grp+tig)%32 -> conflict-free
#define GT_SMEM (2 * 128 * SPITCH * 4)    // 200704 bytes

__device__ __forceinline__ void mma1688_tf32(float* c, const uint32_t* a, const uint32_t* b) {
    asm volatile(
        "mma.sync.aligned.m16n8k8.row.col.f32.tf32.tf32.f32 "
        "{%0,%1,%2,%3}, {%4,%5,%6,%7}, {%8,%9}, {%0,%1,%2,%3};"
        : "+f"(c[0]), "+f"(c[1]), "+f"(c[2]), "+f"(c[3])
        : "r"(a[0]), "r"(a[1]), "r"(a[2]), "r"(a[3]), "r"(b[0]), "r"(b[1]));
}

__global__ __launch_bounds__(256, 1) void gemm_mma_kernel(const float* __restrict__ hb2) {
    extern __shared__ __align__(16) float sm[];
    float* As = sm;                        // [128][SPITCH], cols 0..191 valid
    float* Bs = sm + 128 * SPITCH;

    const int tid = threadIdx.x;
    const int wid = tid >> 5;
    const int lid = tid & 31;
    const int b0 = blockIdx.x * 128;
    const int j0 = blockIdx.y * 128;

    // Load both full tiles (128x192 fp32 each) as uint4 segments
#pragma unroll
    for (int l = 0; l < 24; l++) {
        int idx = tid + l * 256;          // 0..6143
        int m = idx / 48;
        int seg = idx - m * 48;           // 0..47 (4 floats each)
        uint4 va = *(const uint4*)(g_A + (size_t)(b0 + m) * K2 + seg * 4);
        *(uint4*)(As + m * SPITCH + seg * 4) = va;
        uint4 vb = *(const uint4*)(g_B + (size_t)(j0 + m) * K2 + seg * 4);
        *(uint4*)(Bs + m * SPITCH + seg * 4) = vb;
    }
    __syncthreads();

    const int wm = (wid & 3) * 32;        // warp row base within tile
    const int wn = (wid >> 2) * 64;       // warp col base within tile
    const int grp = lid >> 2;             // 0..7
    const int tig = lid & 3;              // 0..3

    float acc[2][8][4];
#pragma unroll
    for (int mi = 0; mi < 2; mi++)
#pragma unroll
        for (int ni = 0; ni < 8; ni++)
#pragma unroll
            for (int q = 0; q < 4; q++) acc[mi][ni][q] = 0.0f;

    // 3 split terms: (Ahi,Bhi), (Ahi,Blo), (Alo,Bhi)
    const int AOFF[3] = {0, 0, 96};
    const int BOFF[3] = {0, 96, 0};

#pragma unroll
    for (int cterm = 0; cterm < 3; cterm++) {
        const float* Ab = As + AOFF[cterm];
        const float* Bb = Bs + BOFF[cterm];
#pragma unroll
        for (int ks = 0; ks < 12; ks++) {
            const int k = ks * 8 + tig;

            // A fragment (m16n8k8 tf32): a0=[grp][tig], a1=[grp+8][tig],
            //                            a2=[grp][tig+4], a3=[grp+8][tig+4]
            uint32_t a[2][4];
#pragma unroll
            for (int mi = 0; mi < 2; mi++) {
                int r = wm + mi * 16 + grp;
                a[mi][0] = *(const uint32_t*)(Ab + r * SPITCH + k);
                a[mi][1] = *(const uint32_t*)(Ab + (r + 8) * SPITCH + k);
                a[mi][2] = *(const uint32_t*)(Ab + r * SPITCH + k + 4);
                a[mi][3] = *(const uint32_t*)(Ab + (r + 8) * SPITCH + k + 4);
            }
            // B fragment: b0=[k=tig][n=grp], b1=[k=tig+4][n=grp]; Bs is [n][k]
            uint32_t b[8][2];
#pragma unroll
            for (int ni = 0; ni < 8; ni++) {
                int n = wn + ni * 8 + grp;
                b[ni][0] = *(const uint32_t*)(Bb + n * SPITCH + k);
                b[ni][1] = *(const uint32_t*)(Bb + n * SPITCH + k + 4);
            }
#pragma unroll
            for (int mi = 0; mi < 2; mi++)
#pragma unroll
                for (int ni = 0; ni < 8; ni++)
                    mma1688_tf32(acc[mi][ni], a[mi], b[ni]);
        }
    }

    // Epilogue: bias add + float2 stores
#pragma unroll
    for (int ni = 0; ni < 8; ni++) {
        const int col = j0 + wn + ni * 8 + 2 * tig;
        const float bx = (col < NPARAM) ? hb2[col] : 0.0f;
        const float by = (col + 1 < NPARAM) ? hb2[col + 1] : 0.0f;
#pragma unroll
        for (int mi = 0; mi < 2; mi++) {
            const int r0 = b0 + wm + mi * 16 + grp;
            *(float2*)(g_params + (size_t)r0 * PPAD + col) =
                make_float2(acc[mi][ni][0] + bx, acc[mi][ni][1] + by);
            *(float2*)(g_params + (size_t)(r0 + 8) * PPAD + col) =
                make_float2(acc[mi][ni][2] + bx, acc[mi][ni][3] + by);
        }
    }
}

// ---------------------------------------------------------------------------
// Adam loop (R7 scalar version — known good).  96 threads / 2 samples per
// block; thread i owns rows i of w1/w2 in registers; activations via smem.
// ---------------------------------------------------------------------------
__global__ __launch_bounds__(96, 4) void adam_kernel(float* __restrict__ out) {
    __shared__ __align__(16) float h0s[2][48];
    __shared__ __align__(16) float dh0s[2][48];
    __shared__ __align__(16) float h1s[2][48];
    __shared__ __align__(16) float dh1s[2][48];
    __shared__ __align__(16) float part[2][48];

    const int tid = threadIdx.x;
    const int s = tid / 48;
    const int i = tid - s * 48;
    const int sample = blockIdx.x * 2 + s;

    const float* p = g_params + (size_t)sample * PPAD;

    const float w0i = p[i];
    const float b0i = p[48 + i];
    const float b1i = p[2400 + i];
    const float b2i = p[4752 + i];
    const float w3i = p[4800 + i];

    float w1r[48], w2r[48];
    {
        const float4* p1 = (const float4*)(p + 96 + i * 48);
        const float4* p2 = (const float4*)(p + 2448 + i * 48);
#pragma unroll
        for (int q = 0; q < 12; q++) {
            float4 a = p1[q];
            w1r[4 * q + 0] = a.x; w1r[4 * q + 1] = a.y; w1r[4 * q + 2] = a.z; w1r[4 * q + 3] = a.w;
            float4 b = p2[q];
            w2r[4 * q + 0] = b.x; w2r[4 * q + 1] = b.y; w2r[4 * q + 2] = b.z; w2r[4 * q + 3] = b.w;
        }
    }

    float y = 0.0f, mA = 0.0f, vA = 0.0f, pb1 = 1.0f, pb2 = 1.0f;

#pragma unroll 1
    for (int t = 0; t < NSTEPS; t++) {
        float z0 = fmaf(w0i, y, b0i);
        float s0 = sigmoidf(z0);
        h0s[s][i]  = z0 * s0;
        dh0s[s][i] = (s0 + z0 * s0 * (1.0f - s0)) * w0i;
        __syncthreads();

        float acc = b1i, dacc = 0.0f;
        {
            const float4* h4 = (const float4*)h0s[s];
            const float4* d4 = (const float4*)dh0s[s];
#pragma unroll
            for (int q = 0; q < 12; q++) {
                float4 hv = h4[q], dv = d4[q];
                acc  = fmaf(w1r[4 * q + 0], hv.x, acc);
                acc  = fmaf(w1r[4 * q + 1], hv.y, acc);
                acc  = fmaf(w1r[4 * q + 2], hv.z, acc);
                acc  = fmaf(w1r[4 * q + 3], hv.w, acc);
                dacc = fmaf(w1r[4 * q + 0], dv.x, dacc);
                dacc = fmaf(w1r[4 * q + 1], dv.y, dacc);
                dacc = fmaf(w1r[4 * q + 2], dv.z, dacc);
                dacc = fmaf(w1r[4 * q + 3], dv.w, dacc);
            }
        }
        float s1 = sigmoidf(acc);
        h1s[s][i]  = acc * s1;
        dh1s[s][i] = (s1 + acc * s1 * (1.0f - s1)) * dacc;
        __syncthreads();

        acc = b2i; dacc = 0.0f;
        {
            const float4* h4 = (const float4*)h1s[s];
            const float4* d4 = (const float4*)dh1s[s];
#pragma unroll
            for (int q = 0; q < 12; q++) {
                float4 hv = h4[q], dv = d4[q];
                acc  = fmaf(w2r[4 * q + 0], hv.x, acc);
                acc  = fmaf(w2r[4 * q + 1], hv.y, acc);
                acc  = fmaf(w2r[4 * q + 2], hv.z, acc);
                acc  = fmaf(w2r[4 * q + 3], hv.w, acc);
                dacc = fmaf(w2r[4 * q + 0], dv.x, dacc);
                dacc = fmaf(w2r[4 * q + 1], dv.y, dacc);
                dacc = fmaf(w2r[4 * q + 2], dv.z, dacc);
                dacc = fmaf(w2r[4 * q + 3], dv.w, dacc);
            }
        }
        float s2 = sigmoidf(acc);
        part[s][i] = w3i * ((s2 + acc * s2 * (1.0f - s2)) * dacc);
        __syncthreads();

        float g = 0.0f;
        {
            const float4* q4 = (const float4*)part[s];
#pragma unroll
            for (int q = 0; q < 12; q++) {
                float4 pv = q4[q];
                g += ((pv.x + pv.y) + (pv.z + pv.w));
            }
        }

        pb1 *= 0.9f;
        pb2 *= 0.999f;
        mA = 0.9f * mA + 0.1f * g;
        vA = 0.999f * vA + 0.001f * g * g;
        float mh = mA / (1.0f - pb1);
        float vh = vA / (1.0f - pb2);
        y -= 0.1f * mh / (sqrtf(vh) + 1e-8f);
    }

    if (i == 0) out[sample] = y;
}

// ---------------------------------------------------------------------------
extern "C" void kernel_launch(void* const* d_in, const int* in_sizes, int n_in,
                              void* d_out, int out_size) {
    const float* x   = (const float*)d_in[0];   // (8192,1)
    const float* c   = (const float*)d_in[1];   // (8192,1)
    const float* hw1 = (const float*)d_in[2];   // (96,2)
    const float* hb1 = (const float*)d_in[3];   // (96,)
    const float* hw2 = (const float*)d_in[4];   // (4849,96)
    const float* hb2 = (const float*)d_in[5];   // (4849,)
    float* out = (float*)d_out;                 // (8192,1)

    (void)in_sizes; (void)n_in; (void)out_size;

    cudaFuncSetAttribute(gemm_mma_kernel,
                         cudaFuncAttributeMaxDynamicSharedMemorySize, GT_SMEM);

    prep_a_kernel<<<(NB * NH + 255) / 256, 256>>>(x, c, hw1, hb1);
    prep_b_kernel<<<(NPPAD * NH + 255) / 256, 256>>>(hw2);

    dim3 grid(NB / 128, NPPAD / 128);           // (64, 38)
    gemm_mma_kernel<<<grid, 256, GT_SMEM>>>(hb2);

    adam_kernel<<<NB / 2, 96>>>(out);
}